// round 4
// baseline (speedup 1.0000x reference)
#include <cuda_runtime.h>
#include <cuda_bf16.h>

// Problem constants (fixed by the dataset)
#define NT 4            // B*C trees
#define NN 262144       // nodes per tree (2^18)
#define NPIX (1024*1024)
#define TOTN (NT*NN)            // 1,048,576 nodes total
#define TOTP (NT*NPIX)          // 4,194,304 pixels total

// Scratch: packed (parent, c) jump tables (ping-pong) and per-node values.
// int2.x = jump-parent index (0 = root reached), int2.y = float bits of partial path sum
__device__ int2  g_bufA[TOTN];
__device__ int2  g_bufB[TOTN];
__device__ float g_v[TOTN];

// ---------------------------------------------------------------------------
// K1 (ILP4): c[i] = sigmoid(clamp(1000*(attr-thr),-12,12)) * (levels[i]-levels[p])
//            c[0] = levels[0]; pack (parent, c).
// ---------------------------------------------------------------------------
__global__ void k_build(const float* __restrict__ attr,
                        const float* __restrict__ levels,
                        const float* __restrict__ thr,
                        const int*   __restrict__ parent)
{
    int t = blockIdx.x * blockDim.x + threadIdx.x;
    if (t >= TOTN / 4) return;
    int idx = t * 4;                       // NN % 4 == 0 -> same tree for all 4
    int base = idx & ~(NN - 1);
    int i0 = idx & (NN - 1);

    float4 lv = __ldg(reinterpret_cast<const float4*>(levels) + t);
    float4 at = __ldg(reinterpret_cast<const float4*>(attr) + t);
    int4   pp = __ldg(reinterpret_cast<const int4*>(parent) + t);
    float  th = __ldg(thr);

    // 4 independent gathers of levels[parent]
    float lp0 = __ldg(&levels[base + pp.x]);
    float lp1 = __ldg(&levels[base + pp.y]);
    float lp2 = __ldg(&levels[base + pp.z]);
    float lp3 = __ldg(&levels[base + pp.w]);

    float l[4] = {lv.x, lv.y, lv.z, lv.w};
    float a[4] = {at.x, at.y, at.z, at.w};
    float lp[4] = {lp0, lp1, lp2, lp3};
    int   p[4] = {pp.x, pp.y, pp.z, pp.w};

    int2 out[4];
#pragma unroll
    for (int k = 0; k < 4; k++) {
        float z = 1000.0f * (a[k] - th);
        z = fminf(fmaxf(z, -12.0f), 12.0f);
        float s = 1.0f / (1.0f + __expf(-z));
        float c = s * (l[k] - lp[k]);
        int pk = p[k];
        if (i0 + k == 0) { pk = 0; c = l[k]; }   // root: c[0] = levels[0]
        out[k] = make_int2(pk, __float_as_int(c));
    }
    reinterpret_cast<int4*>(g_bufA)[t * 2 + 0] = make_int4(out[0].x, out[0].y, out[1].x, out[1].y);
    reinterpret_cast<int4*>(g_bufA)[t * 2 + 1] = make_int4(out[2].x, out[2].y, out[3].x, out[3].y);
}

// ---------------------------------------------------------------------------
// K2..K4 (ILP4): jump doubling with 4 independent gathers in flight.
// p==0 means chain terminated (root's c added at climb start).
// ---------------------------------------------------------------------------
__global__ void k_double(const int2* __restrict__ in, int2* __restrict__ out)
{
    int t = blockIdx.x * blockDim.x + threadIdx.x;
    if (t >= TOTN / 4) return;
    int idx = t * 4;
    int base = idx & ~(NN - 1);

    int4 r0 = __ldg(reinterpret_cast<const int4*>(in) + t * 2 + 0);
    int4 r1 = __ldg(reinterpret_cast<const int4*>(in) + t * 2 + 1);
    int2 a[4] = { make_int2(r0.x, r0.y), make_int2(r0.z, r0.w),
                  make_int2(r1.x, r1.y), make_int2(r1.z, r1.w) };

    // issue all 4 gathers before consuming any
    int2 b[4];
#pragma unroll
    for (int k = 0; k < 4; k++)
        b[k] = __ldg(&in[base + (a[k].x != 0 ? a[k].x : 0)]);

#pragma unroll
    for (int k = 0; k < 4; k++) {
        if (a[k].x != 0) {
            a[k].y = __float_as_int(__int_as_float(a[k].y) + __int_as_float(b[k].y));
            a[k].x = b[k].x;
        }
    }
    reinterpret_cast<int4*>(out)[t * 2 + 0] = make_int4(a[0].x, a[0].y, a[1].x, a[1].y);
    reinterpret_cast<int4*>(out)[t * 2 + 1] = make_int4(a[2].x, a[2].y, a[3].x, a[3].y);
}

// ---------------------------------------------------------------------------
// K5 (ILP4): 4 interleaved serial climbs of the jump-8 table -> MLP 4.
// v[i] = c[0] + sum of jump sums along chain.
// ---------------------------------------------------------------------------
__global__ void k_climb(const int2* __restrict__ jp)
{
    int t = blockIdx.x * blockDim.x + threadIdx.x;
    if (t >= TOTN / 4) return;
    int idx = t * 4;
    int base = idx & ~(NN - 1);

    float c0 = __int_as_float(__ldg(&jp[base].y));   // c[0] = levels[0]
    int   j[4];
    float acc[4];
#pragma unroll
    for (int k = 0; k < 4; k++) { j[k] = (idx + k) & (NN - 1); acc[k] = c0; }

    while ((j[0] | j[1] | j[2] | j[3]) != 0) {
        int2 a[4];
#pragma unroll
        for (int k = 0; k < 4; k++)
            a[k] = __ldg(&jp[base + j[k]]);          // 4 loads in flight
#pragma unroll
        for (int k = 0; k < 4; k++) {
            if (j[k] != 0) {
                acc[k] += __int_as_float(a[k].y);
                j[k] = a[k].x;
            }
        }
    }
    reinterpret_cast<float4*>(g_v)[t] = make_float4(acc[0], acc[1], acc[2], acc[3]);
}

// ---------------------------------------------------------------------------
// K6: y[p] = v[tree(p)*NN + pixel_to_node[p]], 4 pixels per thread
// ---------------------------------------------------------------------------
__global__ void k_gather(const int* __restrict__ ptn, float* __restrict__ y)
{
    int q = blockIdx.x * blockDim.x + threadIdx.x;   // quad index
    if (q >= TOTP / 4) return;
    int p0 = q * 4;
    int base = (p0 >> 20) << 18;                     // tree * NN  (NPIX = 2^20)

    int4 n = __ldg(reinterpret_cast<const int4*>(ptn) + q);
    float4 o;
    o.x = __ldg(&g_v[base + n.x]);
    o.y = __ldg(&g_v[base + n.y]);
    o.z = __ldg(&g_v[base + n.z]);
    o.w = __ldg(&g_v[base + n.w]);
    reinterpret_cast<float4*>(y)[q] = o;
}

// ---------------------------------------------------------------------------
extern "C" void kernel_launch(void* const* d_in, const int* in_sizes, int n_in,
                              void* d_out, int out_size)
{
    // metadata order: x, attr_norm, levels, thr, parent, pixel_to_node
    const float* attr   = (const float*)d_in[1];
    const float* levels = (const float*)d_in[2];
    const float* thr    = (const float*)d_in[3];
    const int*   parent = (const int*)d_in[4];
    const int*   ptn    = (const int*)d_in[5];
    float*       y      = (float*)d_out;

    void *pA = nullptr, *pB = nullptr;
    cudaGetSymbolAddress(&pA, g_bufA);
    cudaGetSymbolAddress(&pB, g_bufB);
    int2* A = (int2*)pA;
    int2* B = (int2*)pB;

    const int TPB = 256;
    const int gbN4 = (TOTN / 4 + TPB - 1) / TPB;

    k_build<<<gbN4, TPB>>>(attr, levels, thr, parent);
    k_double<<<gbN4, TPB>>>(A, B);   // jump 2
    k_double<<<gbN4, TPB>>>(B, A);   // jump 4
    k_double<<<gbN4, TPB>>>(A, B);   // jump 8
    k_climb<<<gbN4, TPB>>>(B);

    const int gbP = (TOTP / 4 + TPB - 1) / TPB;
    k_gather<<<gbP, TPB>>>(ptn, y);
}